// round 1
// baseline (speedup 1.0000x reference)
#include <cuda_runtime.h>
#include <cstdint>

#define NN 100000
#define NE 625000
#define DD 128
#define NL 10

// ---------------- scratch (device globals; no allocation allowed) ----------
static __device__ float g_bufA[(size_t)NN * DD];
static __device__ float g_bufB[(size_t)NN * DD];
static __device__ float g_agg[(size_t)NN * DD];
static __device__ float g_invdeg[NN];
static __device__ int   g_cnt[NN];
static __device__ int   g_fill[NN];
static __device__ int   g_rowptr[NN + 1];
static __device__ int   g_csr[NE];
static __device__ int   g_bsums[128];

// ---------------- packed f32x2 helpers -------------------------------------
__device__ __forceinline__ unsigned long long pack2(float x) {
    unsigned long long d;
    asm("mov.b64 %0, {%1, %2};" : "=l"(d)
        : "r"(__float_as_uint(x)), "r"(__float_as_uint(x)));
    return d;
}
__device__ __forceinline__ void fma2(unsigned long long& d,
                                     unsigned long long a,
                                     unsigned long long b) {
    asm("fma.rn.f32x2 %0, %1, %2, %0;" : "+l"(d) : "l"(a), "l"(b));
}

// ---------------- CSR construction -----------------------------------------
__global__ void k_zero(void) {
    int i = blockIdx.x * blockDim.x + threadIdx.x;
    if (i < NN) { g_cnt[i] = 0; g_fill[i] = 0; }
}

__global__ void k_hist(const int* __restrict__ dst) {
    int e = blockIdx.x * blockDim.x + threadIdx.x;
    if (e < NE) atomicAdd(&g_cnt[dst[e]], 1);
}

#define SCAN_B 1024
__global__ void k_scan1(void) {
    __shared__ int sh[SCAN_B];
    int i = blockIdx.x * SCAN_B + threadIdx.x;
    int v = (i < NN) ? g_cnt[i] : 0;
    sh[threadIdx.x] = v;
    __syncthreads();
    for (int off = 1; off < SCAN_B; off <<= 1) {
        int t = (threadIdx.x >= off) ? sh[threadIdx.x - off] : 0;
        __syncthreads();
        sh[threadIdx.x] += t;
        __syncthreads();
    }
    if (i < NN) g_rowptr[i] = sh[threadIdx.x] - v;   // block-local exclusive
    if (threadIdx.x == SCAN_B - 1) g_bsums[blockIdx.x] = sh[threadIdx.x];
}

__global__ void k_scan2(int nb) {
    if (threadIdx.x == 0 && blockIdx.x == 0) {
        int run = 0;
        for (int i = 0; i < nb; i++) { int v = g_bsums[i]; g_bsums[i] = run; run += v; }
    }
}

__global__ void k_scan3(void) {
    int i = blockIdx.x * blockDim.x + threadIdx.x;
    if (i < NN) {
        g_rowptr[i] += g_bsums[i / SCAN_B];
        int c = g_cnt[i];
        g_invdeg[i] = 1.0f / (float)(c > 0 ? c : 1);
    }
    if (i == 0) g_rowptr[NN] = NE;
}

__global__ void k_scatter(const int* __restrict__ src, const int* __restrict__ dst) {
    int e = blockIdx.x * blockDim.x + threadIdx.x;
    if (e >= NE) return;
    int d = dst[e];
    int pos = atomicAdd(&g_fill[d], 1);
    g_csr[g_rowptr[d] + pos] = src[e];
}

// ---------------- mean aggregation (gather, atomic-free) --------------------
// one warp per dst node; each lane owns 4 contiguous columns (float4)
__global__ void k_agg(const float* __restrict__ xin) {
    int node = blockIdx.x * 8 + (threadIdx.x >> 5);
    if (node >= NN) return;
    int lane = threadIdx.x & 31;
    int beg = g_rowptr[node];
    int end = g_rowptr[node + 1];
    float4 acc = make_float4(0.f, 0.f, 0.f, 0.f);
    int t = beg;
    for (; t + 1 < end; t += 2) {
        int s0 = g_csr[t];
        int s1 = g_csr[t + 1];
        float4 v0 = *(const float4*)(xin + (size_t)s0 * DD + lane * 4);
        float4 v1 = *(const float4*)(xin + (size_t)s1 * DD + lane * 4);
        acc.x += v0.x + v1.x; acc.y += v0.y + v1.y;
        acc.z += v0.z + v1.z; acc.w += v0.w + v1.w;
    }
    if (t < end) {
        int s0 = g_csr[t];
        float4 v0 = *(const float4*)(xin + (size_t)s0 * DD + lane * 4);
        acc.x += v0.x; acc.y += v0.y; acc.z += v0.z; acc.w += v0.w;
    }
    float sc = g_invdeg[node];
    float4 r = make_float4(acc.x * sc, acc.y * sc, acc.z * sc, acc.w * sc);
    *(float4*)(g_agg + (size_t)node * DD + lane * 4) = r;
}

// ---------------- fused dual GEMM: out = agg*Wl + x*Wr + b (+relu) ----------
// BM=128, BN=128, BK=32, 256 threads, 8x8 microtile, f32x2 inner product
__global__ __launch_bounds__(256, 2)
void k_gemm(const float* __restrict__ A0,  // agg
            const float* __restrict__ A1,  // x
            const float* __restrict__ W0,  // Wl layer slice [128][128]
            const float* __restrict__ W1,  // Wr layer slice
            const float* __restrict__ bias,
            float* __restrict__ out,
            int relu) {
    __shared__ float As[32][129];   // transposed: As[k][row]; 129 => conflict-free stores
    __shared__ float Ws[32][128];   // Ws[k][col]

    const int tid = threadIdx.x;
    const int tx = tid & 15;        // col group
    const int ty = tid >> 4;        // row group
    const int rowBase = blockIdx.x * 128;

    // loader coords
    const int arow = tid >> 3;          // 0..31, +32 per pass
    const int ak4  = (tid & 7) * 4;     // k offset within tile
    const int wk   = tid >> 5;          // 0..7, +8 per pass
    const int wc4  = (tid & 31) * 4;    // col offset

    unsigned long long acc[8][4];
    #pragma unroll
    for (int i = 0; i < 8; i++)
        #pragma unroll
        for (int j = 0; j < 4; j++) acc[i][j] = 0ULL;

    #pragma unroll 1
    for (int kb = 0; kb < 8; ++kb) {
        const float* Asrc; const float* Wsrc; int koff;
        if (kb < 4) { Asrc = A0; Wsrc = W0; koff = kb * 32; }
        else        { Asrc = A1; Wsrc = W1; koff = (kb - 4) * 32; }

        __syncthreads();
        #pragma unroll
        for (int p = 0; p < 4; ++p) {
            int r = arow + p * 32;
            int grow = rowBase + r;
            float4 v = make_float4(0.f, 0.f, 0.f, 0.f);
            if (grow < NN)
                v = *(const float4*)(Asrc + (size_t)grow * DD + koff + ak4);
            As[ak4 + 0][r] = v.x;
            As[ak4 + 1][r] = v.y;
            As[ak4 + 2][r] = v.z;
            As[ak4 + 3][r] = v.w;
        }
        #pragma unroll
        for (int p = 0; p < 4; ++p) {
            int k = wk + p * 8;
            *(float4*)(&Ws[k][wc4]) =
                *(const float4*)(Wsrc + (size_t)(koff + k) * DD + wc4);
        }
        __syncthreads();

        #pragma unroll
        for (int k = 0; k < 32; ++k) {
            // W pairs: 16B-aligned, reinterpret as two packed f32x2
            ulonglong2 wlo = *(const ulonglong2*)(&Ws[k][tx * 8]);
            ulonglong2 whi = *(const ulonglong2*)(&Ws[k][tx * 8 + 4]);
            unsigned long long w2[4] = {wlo.x, wlo.y, whi.x, whi.y};
            float a0 = As[k][ty * 8 + 0], a1 = As[k][ty * 8 + 1];
            float a2 = As[k][ty * 8 + 2], a3 = As[k][ty * 8 + 3];
            float a4 = As[k][ty * 8 + 4], a5 = As[k][ty * 8 + 5];
            float a6 = As[k][ty * 8 + 6], a7 = As[k][ty * 8 + 7];
            unsigned long long aa[8] = {pack2(a0), pack2(a1), pack2(a2), pack2(a3),
                                        pack2(a4), pack2(a5), pack2(a6), pack2(a7)};
            #pragma unroll
            for (int i = 0; i < 8; i++)
                #pragma unroll
                for (int j = 0; j < 4; j++)
                    fma2(acc[i][j], aa[i], w2[j]);
        }
    }

    // epilogue
    float bv[8];
    *(float4*)bv       = *(const float4*)(bias + tx * 8);
    *(float4*)(bv + 4) = *(const float4*)(bias + tx * 8 + 4);

    #pragma unroll
    for (int i = 0; i < 8; i++) {
        int row = rowBase + ty * 8 + i;
        if (row < NN) {
            float o[8];
            #pragma unroll
            for (int j = 0; j < 4; j++) {
                union { unsigned long long u; float2 f; } c;
                c.u = acc[i][j];
                o[2 * j]     = c.f.x + bv[2 * j];
                o[2 * j + 1] = c.f.y + bv[2 * j + 1];
            }
            if (relu) {
                #pragma unroll
                for (int j = 0; j < 8; j++) o[j] = fmaxf(o[j], 0.f);
            }
            *(float4*)(out + (size_t)row * DD + tx * 8)     = *(float4*)o;
            *(float4*)(out + (size_t)row * DD + tx * 8 + 4) = *(float4*)(o + 4);
        }
    }
}

// ---------------- host driver (graph-capturable) ----------------------------
extern "C" void kernel_launch(void* const* d_in, const int* in_sizes, int n_in,
                              void* d_out, int out_size) {
    const float* x  = (const float*)d_in[0];
    const float* Wl = (const float*)d_in[1];
    const float* Wr = (const float*)d_in[2];
    const float* b  = (const float*)d_in[3];
    const int* ei   = (const int*)d_in[4];
    const int* src  = ei;
    const int* dst  = ei + NE;

    float *bufA, *bufB, *agg;
    cudaGetSymbolAddress((void**)&bufA, g_bufA);
    cudaGetSymbolAddress((void**)&bufB, g_bufB);
    cudaGetSymbolAddress((void**)&agg,  g_agg);

    const int NB_SCAN = (NN + SCAN_B - 1) / SCAN_B;   // 98

    // ---- CSR build (once per launch) ----
    k_zero<<<(NN + 255) / 256, 256>>>();
    k_hist<<<(NE + 255) / 256, 256>>>(dst);
    k_scan1<<<NB_SCAN, SCAN_B>>>();
    k_scan2<<<1, 32>>>(NB_SCAN);
    k_scan3<<<(NN + 255) / 256, 256>>>();
    k_scatter<<<(NE + 255) / 256, 256>>>(src, dst);

    // ---- 10 layers ----
    const float* cur = x;
    float* nxt = bufA;
    const int gemmBlocks = (NN + 127) / 128;   // 782
    for (int i = 0; i < NL; i++) {
        k_agg<<<(NN + 7) / 8, 256>>>(cur);
        float* outp = (i == NL - 1) ? (float*)d_out : nxt;
        k_gemm<<<gemmBlocks, 256>>>(agg, cur,
                                    Wl + (size_t)i * DD * DD,
                                    Wr + (size_t)i * DD * DD,
                                    b + (size_t)i * DD,
                                    outp, (i < NL - 1) ? 1 : 0);
        cur = outp;
        nxt = (nxt == bufA) ? bufB : bufA;
    }
}

// round 3
// speedup vs baseline: 1.3881x; 1.3881x over previous
#include <cuda_runtime.h>
#include <cuda_bf16.h>
#include <cstdint>

#define NN 100000
#define NE 625000
#define DD 128
#define NL 10

// ---------------- scratch (device globals; no allocation allowed) ----------
static __device__ unsigned short g_ha[(size_t)NN * DD];
static __device__ unsigned short g_la[(size_t)NN * DD];
static __device__ unsigned short g_hb[(size_t)NN * DD];
static __device__ unsigned short g_lb[(size_t)NN * DD];
static __device__ unsigned short g_aggh[(size_t)NN * DD];
static __device__ unsigned short g_aggl[(size_t)NN * DD];
// pre-split W, smem image: per layer [2 planes][256 k][136 cols(272B rows)]
static __device__ __align__(16) unsigned short g_WT[(size_t)NL * 69632];
static __device__ float g_invdeg[NN];
static __device__ int   g_cnt[NN];
static __device__ int   g_fill[NN];
static __device__ int   g_rowptr[NN + 1];
static __device__ int   g_csr[NE];
static __device__ int   g_bsums[128];

// ---------------- PTX helpers ----------------------------------------------
__device__ __forceinline__ uint32_t smem_u32(const void* p) {
    uint32_t a;
    asm("{ .reg .u64 t; cvta.to.shared.u64 t, %1; cvt.u32.u64 %0, t; }"
        : "=r"(a) : "l"(p));
    return a;
}
__device__ __forceinline__ void ldsm_x4(uint32_t* r, uint32_t addr) {
    asm volatile("ldmatrix.sync.aligned.m8n8.x4.shared.b16 {%0,%1,%2,%3}, [%4];"
                 : "=r"(r[0]), "=r"(r[1]), "=r"(r[2]), "=r"(r[3]) : "r"(addr));
}
__device__ __forceinline__ void ldsm_x4t(uint32_t* r, uint32_t addr) {
    asm volatile("ldmatrix.sync.aligned.m8n8.x4.trans.shared.b16 {%0,%1,%2,%3}, [%4];"
                 : "=r"(r[0]), "=r"(r[1]), "=r"(r[2]), "=r"(r[3]) : "r"(addr));
}
__device__ __forceinline__ void mma16816(float* d, const uint32_t* a,
                                         uint32_t b0, uint32_t b1) {
    asm volatile(
        "mma.sync.aligned.m16n8k16.row.col.f32.bf16.bf16.f32 "
        "{%0,%1,%2,%3}, {%4,%5,%6,%7}, {%8,%9}, {%0,%1,%2,%3};"
        : "+f"(d[0]), "+f"(d[1]), "+f"(d[2]), "+f"(d[3])
        : "r"(a[0]), "r"(a[1]), "r"(a[2]), "r"(a[3]), "r"(b0), "r"(b1));
}
__device__ __forceinline__ void cp16(uint32_t dst, const void* src, uint32_t srcsz) {
    asm volatile("cp.async.cg.shared.global [%0], [%1], 16, %2;"
                 :: "r"(dst), "l"(src), "r"(srcsz) : "memory");
}
#define CP_COMMIT() asm volatile("cp.async.commit_group;" ::: "memory")
#define CP_WAIT(n)  asm volatile("cp.async.wait_group %0;" :: "n"(n) : "memory")

// ---------------- CSR construction -----------------------------------------
__global__ void k_zero(void) {
    int i = blockIdx.x * blockDim.x + threadIdx.x;
    if (i < NN) { g_cnt[i] = 0; g_fill[i] = 0; }
}
__global__ void k_hist(const int* __restrict__ dst) {
    int e = blockIdx.x * blockDim.x + threadIdx.x;
    if (e < NE) atomicAdd(&g_cnt[dst[e]], 1);
}
#define SCAN_B 1024
__global__ void k_scan1(void) {
    __shared__ int sh[SCAN_B];
    int i = blockIdx.x * SCAN_B + threadIdx.x;
    int v = (i < NN) ? g_cnt[i] : 0;
    sh[threadIdx.x] = v;
    __syncthreads();
    for (int off = 1; off < SCAN_B; off <<= 1) {
        int t = (threadIdx.x >= off) ? sh[threadIdx.x - off] : 0;
        __syncthreads();
        sh[threadIdx.x] += t;
        __syncthreads();
    }
    if (i < NN) g_rowptr[i] = sh[threadIdx.x] - v;
    if (threadIdx.x == SCAN_B - 1) g_bsums[blockIdx.x] = sh[threadIdx.x];
}
__global__ void k_scan2(int nb) {
    if (threadIdx.x == 0 && blockIdx.x == 0) {
        int run = 0;
        for (int i = 0; i < nb; i++) { int v = g_bsums[i]; g_bsums[i] = run; run += v; }
    }
}
__global__ void k_scan3(void) {
    int i = blockIdx.x * blockDim.x + threadIdx.x;
    if (i < NN) {
        g_rowptr[i] += g_bsums[i / SCAN_B];
        int c = g_cnt[i];
        g_invdeg[i] = 1.0f / (float)(c > 0 ? c : 1);
    }
    if (i == 0) g_rowptr[NN] = NE;
}
__global__ void k_scatter(const int* __restrict__ src, const int* __restrict__ dst) {
    int e = blockIdx.x * blockDim.x + threadIdx.x;
    if (e >= NE) return;
    int d = dst[e];
    int pos = atomicAdd(&g_fill[d], 1);
    g_csr[g_rowptr[d] + pos] = src[e];
}

// ---------------- fp32 -> (hi, lo) bf16 split ------------------------------
__device__ __forceinline__ void split2(float v, unsigned short& h, unsigned short& l) {
    __nv_bfloat16 hb = __float2bfloat16(v);
    float r = v - __bfloat162float(hb);
    __nv_bfloat16 lb = __float2bfloat16(r);
    h = __bfloat16_as_ushort(hb);
    l = __bfloat16_as_ushort(lb);
}

__global__ void k_split(const float* __restrict__ x,
                        unsigned short* __restrict__ xh,
                        unsigned short* __restrict__ xl) {
    size_t i = ((size_t)blockIdx.x * blockDim.x + threadIdx.x) * 4;
    if (i >= (size_t)NN * DD) return;
    float4 v = *(const float4*)(x + i);
    unsigned short h[4], l[4];
    split2(v.x, h[0], l[0]); split2(v.y, h[1], l[1]);
    split2(v.z, h[2], l[2]); split2(v.w, h[3], l[3]);
    *(uint2*)(xh + i) = *(uint2*)h;
    *(uint2*)(xl + i) = *(uint2*)l;
}

// ---------------- W pre-split into smem image layout ------------------------
__global__ void k_wprep(const float* __restrict__ Wl, const float* __restrict__ Wr) {
    int idx = blockIdx.x * blockDim.x + threadIdx.x;
    if (idx >= NL * 256 * DD) return;
    int l = idx >> 15;
    int rem = idx & 32767;
    int k = rem >> 7;
    int n = rem & 127;
    float w = (k < 128) ? Wl[(size_t)l * 16384 + (size_t)k * 128 + n]
                        : Wr[(size_t)l * 16384 + (size_t)(k - 128) * 128 + n];
    unsigned short h, lo;
    split2(w, h, lo);
    size_t base = (size_t)l * 69632 + (size_t)k * 136 + n;
    g_WT[base] = h;
    g_WT[base + 34816] = lo;
}

// ---------------- mean aggregation (gather, bf16 hi/lo) ---------------------
__global__ void k_agg(const unsigned short* __restrict__ xh,
                      const unsigned short* __restrict__ xl,
                      unsigned short* __restrict__ ah,
                      unsigned short* __restrict__ al) {
    int node = blockIdx.x * 8 + (threadIdx.x >> 5);
    if (node >= NN) return;
    int lane = threadIdx.x & 31;
    int beg = g_rowptr[node];
    int end = g_rowptr[node + 1];
    float4 acc = make_float4(0.f, 0.f, 0.f, 0.f);
    int t = beg;
    for (; t + 1 < end; t += 2) {
        int s0 = g_csr[t], s1 = g_csr[t + 1];
        uint2 h0 = *(const uint2*)(xh + (size_t)s0 * DD + lane * 4);
        uint2 l0 = *(const uint2*)(xl + (size_t)s0 * DD + lane * 4);
        uint2 h1 = *(const uint2*)(xh + (size_t)s1 * DD + lane * 4);
        uint2 l1 = *(const uint2*)(xl + (size_t)s1 * DD + lane * 4);
        float2 a0 = __bfloat1622float2(*(__nv_bfloat162*)&h0.x);
        float2 a1 = __bfloat1622float2(*(__nv_bfloat162*)&h0.y);
        float2 b0 = __bfloat1622float2(*(__nv_bfloat162*)&l0.x);
        float2 b1 = __bfloat1622float2(*(__nv_bfloat162*)&l0.y);
        float2 c0 = __bfloat1622float2(*(__nv_bfloat162*)&h1.x);
        float2 c1 = __bfloat1622float2(*(__nv_bfloat162*)&h1.y);
        float2 d0 = __bfloat1622float2(*(__nv_bfloat162*)&l1.x);
        float2 d1 = __bfloat1622float2(*(__nv_bfloat162*)&l1.y);
        acc.x += (a0.x + b0.x) + (c0.x + d0.x);
        acc.y += (a0.y + b0.y) + (c0.y + d0.y);
        acc.z += (a1.x + b1.x) + (c1.x + d1.x);
        acc.w += (a1.y + b1.y) + (c1.y + d1.y);
    }
    if (t < end) {
        int s0 = g_csr[t];
        uint2 h0 = *(const uint2*)(xh + (size_t)s0 * DD + lane * 4);
        uint2 l0 = *(const uint2*)(xl + (size_t)s0 * DD + lane * 4);
        float2 a0 = __bfloat1622float2(*(__nv_bfloat162*)&h0.x);
        float2 a1 = __bfloat1622float2(*(__nv_bfloat162*)&h0.y);
        float2 b0 = __bfloat1622float2(*(__nv_bfloat162*)&l0.x);
        float2 b1 = __bfloat1622float2(*(__nv_bfloat162*)&l0.y);
        acc.x += a0.x + b0.x; acc.y += a0.y + b0.y;
        acc.z += a1.x + b1.x; acc.w += a1.y + b1.y;
    }
    float sc = g_invdeg[node];
    unsigned short h[4], l[4];
    split2(acc.x * sc, h[0], l[0]); split2(acc.y * sc, h[1], l[1]);
    split2(acc.z * sc, h[2], l[2]); split2(acc.w * sc, h[3], l[3]);
    *(uint2*)(ah + (size_t)node * DD + lane * 4) = *(uint2*)h;
    *(uint2*)(al + (size_t)node * DD + lane * 4) = *(uint2*)l;
}

// ---------------- persistent mma.sync GEMM ----------------------------------
#define SMEM_W    0
#define W_PLANE   69632
#define SMEM_A    139264
#define A_BUF     18432
#define SMEM_BIAS 176128
#define SMEM_TOT  176640

__global__ __launch_bounds__(256, 1)
void k_gemm_tc(const unsigned short* __restrict__ aggh,
               const unsigned short* __restrict__ aggl,
               const unsigned short* __restrict__ xh,
               const unsigned short* __restrict__ xl,
               const unsigned short* __restrict__ wt,
               const float* __restrict__ bias,
               unsigned short* __restrict__ outh,
               unsigned short* __restrict__ outl,
               float* __restrict__ outf, int last) {
    extern __shared__ char smem[];
    const uint32_t sb = smem_u32(smem);
    const int tid = threadIdx.x;
    const int wid = tid >> 5, lane = tid & 31;
    const int warp_m = wid & 3, warp_n = wid >> 2;

    {   // load W smem image (139264 B = 8704 uint4) + bias
        const uint4* s4 = (const uint4*)wt;
        uint4* d4 = (uint4*)(smem + SMEM_W);
        #pragma unroll
        for (int i = 0; i < 34; i++) d4[tid + i * 256] = s4[tid + i * 256];
        if (tid < 128) ((float*)(smem + SMEM_BIAS))[tid] = bias[tid];
    }
    __syncthreads();

    const uint32_t aBase = sb + SMEM_A +
        (uint32_t)(warp_m * 32 + (lane & 15)) * 144 + (uint32_t)(lane >> 4) * 16;
    const uint32_t bBase = sb + SMEM_W +
        (uint32_t)(lane & 15) * 272 +
        (uint32_t)(warp_n * 64 + (lane >> 4) * 8) * 2;

    const int ldRow = tid >> 1;
    const int ldCol = (tid & 1) * 32;
    const uint32_t ldDst = sb + SMEM_A + (uint32_t)ldRow * 144 + (uint32_t)ldCol * 2;

    const int nTiles = (NN + 127) / 128;
    for (int tile = blockIdx.x; tile < nTiles; tile += (int)gridDim.x) {
        const int rowBase = tile * 128;
        float acc[16][4];
        #pragma unroll
        for (int i = 0; i < 16; i++)
            #pragma unroll
            for (int j = 0; j < 4; j++) acc[i][j] = 0.f;

        const int ldgRow = rowBase + ldRow;
        const uint32_t ok = (ldgRow < NN) ? 16u : 0u;

        {   // issue chunk 0: agg hi, cols 0..63
            const unsigned short* srcp = aggh + (size_t)ldgRow * DD + ldCol;
            #pragma unroll
            for (int i = 0; i < 4; i++) cp16(ldDst + i * 16, srcp + i * 8, ok);
            CP_COMMIT();
        }

        #pragma unroll 1
        for (int c = 0; c < 12; c++) {
            if (c < 11) {
                const int nc = c + 1;
                const unsigned short* ph =
                    ((nc >> 2) == 1) ? ((nc & 2) ? xl : aggl)
                                     : ((nc & 2) ? xh : aggh);
                const int colB = (nc & 1) * 64;
                const unsigned short* srcp = ph + (size_t)ldgRow * DD + colB + ldCol;
                const uint32_t dst = ldDst + (uint32_t)(nc & 1) * A_BUF;
                #pragma unroll
                for (int i = 0; i < 4; i++) cp16(dst + i * 16, srcp + i * 8, ok);
                CP_COMMIT();
                CP_WAIT(1);
            } else {
                CP_WAIT(0);
            }
            __syncthreads();

            const uint32_t aB = aBase + (uint32_t)(c & 1) * A_BUF;
            const uint32_t wB = bBase + (uint32_t)((c < 8) ? 0 : W_PLANE)
                              + (uint32_t)(c & 3) * 64 * 272;
            #pragma unroll
            for (int ks = 0; ks < 4; ks++) {
                uint32_t bf[4][4];
                #pragma unroll
                for (int nb = 0; nb < 4; nb++)
                    ldsm_x4t(bf[nb], wB + (uint32_t)ks * 4352 + (uint32_t)nb * 32);
                uint32_t af[2][4];
                ldsm_x4(af[0], aB + (uint32_t)ks * 32);
                ldsm_x4(af[1], aB + (uint32_t)ks * 32 + 16 * 144);
                #pragma unroll
                for (int mi = 0; mi < 2; mi++)
                    #pragma unroll
                    for (int nb = 0; nb < 4; nb++) {
                        mma16816(acc[mi * 8 + nb * 2],     af[mi], bf[nb][0], bf[nb][1]);
                        mma16816(acc[mi * 8 + nb * 2 + 1], af[mi], bf[nb][2], bf[nb][3]);
                    }
            }
            __syncthreads();
        }

        // ---- epilogue: bias (+relu), split to hi/lo (or fp32 on last) ----
        const float* bs = (const float*)(smem + SMEM_BIAS);
        const int colBase = warp_n * 64 + (lane & 3) * 2;
        const int rBase = rowBase + warp_m * 32 + (lane >> 2);
        #pragma unroll
        for (int mi = 0; mi < 2; mi++) {
            #pragma unroll
            for (int ni = 0; ni < 8; ni++) {
                const int col = colBase + ni * 8;
                const float b0 = bs[col], b1 = bs[col + 1];
                const float* d = acc[mi * 8 + ni];
                #pragma unroll
                for (int rr = 0; rr < 2; rr++) {
                    const int row = rBase + mi * 16 + rr * 8;
                    if (row < NN) {
                        float v0 = d[rr * 2] + b0;
                        float v1 = d[rr * 2 + 1] + b1;
                        if (last) {
                            *(float2*)(outf + (size_t)row * DD + col) =
                                make_float2(v0, v1);
                        } else {
                            v0 = fmaxf(v0, 0.f); v1 = fmaxf(v1, 0.f);
                            unsigned short h0, l0, h1, l1;
                            split2(v0, h0, l0); split2(v1, h1, l1);
                            *(uint32_t*)(outh + (size_t)row * DD + col) =
                                (uint32_t)h0 | ((uint32_t)h1 << 16);
                            *(uint32_t*)(outl + (size_t)row * DD + col) =
                                (uint32_t)l0 | ((uint32_t)l1 << 16);
                        }
                    }
                }
            }
        }
        __syncthreads();
    }
}

// ---------------- host driver (graph-capturable) ----------------------------
extern "C" void kernel_launch(void* const* d_in, const int* in_sizes, int n_in,
                              void* d_out, int out_size) {
    const float* x  = (const float*)d_in[0];
    const float* Wl = (const float*)d_in[1];
    const float* Wr = (const float*)d_in[2];
    const float* b  = (const float*)d_in[3];
    const int* ei   = (const int*)d_in[4];
    const int* src  = ei;
    const int* dst  = ei + NE;

    unsigned short *ha, *la, *hb, *lb, *aggh, *aggl, *wt;
    cudaGetSymbolAddress((void**)&ha, g_ha);
    cudaGetSymbolAddress((void**)&la, g_la);
    cudaGetSymbolAddress((void**)&hb, g_hb);
    cudaGetSymbolAddress((void**)&lb, g_lb);
    cudaGetSymbolAddress((void**)&aggh, g_aggh);
    cudaGetSymbolAddress((void**)&aggl, g_aggl);
    cudaGetSymbolAddress((void**)&wt, g_WT);

    cudaFuncSetAttribute(k_gemm_tc, cudaFuncAttributeMaxDynamicSharedMemorySize, SMEM_TOT);

    const int NB_SCAN = (NN + SCAN_B - 1) / SCAN_B;

    k_zero<<<(NN + 255) / 256, 256>>>();
    k_hist<<<(NE + 255) / 256, 256>>>(dst);
    k_scan1<<<NB_SCAN, SCAN_B>>>();
    k_scan2<<<1, 32>>>(NB_SCAN);
    k_scan3<<<(NN + 255) / 256, 256>>>();
    k_scatter<<<(NE + 255) / 256, 256>>>(src, dst);
    k_split<<<(NN * DD / 4 + 255) / 256, 256>>>(x, ha, la);
    k_wprep<<<(NL * 256 * DD + 255) / 256, 256>>>(Wl, Wr);

    unsigned short *curh = ha, *curl = la, *nxth = hb, *nxtl = lb;
    for (int i = 0; i < NL; i++) {
        k_agg<<<(NN + 7) / 8, 256>>>(curh, curl, aggh, aggl);
        int last = (i == NL - 1) ? 1 : 0;
        k_gemm_tc<<<152, 256, SMEM_TOT>>>(aggh, aggl, curh, curl,
                                          wt + (size_t)i * 69632,
                                          b + (size_t)i * DD,
                                          nxth, nxtl, (float*)d_out, last);
        unsigned short* t;
        t = curh; curh = nxth; nxth = t;
        t = curl; curl = nxtl; nxtl = t;
    }
}

// round 4
// speedup vs baseline: 1.6423x; 1.1831x over previous
#include <cuda_runtime.h>
#include <cuda_bf16.h>
#include <cstdint>

#define NN 100000
#define NE 625000
#define DD 128
#define NL 10

// ---------------- scratch (device globals; no allocation allowed) ----------
// packed activations: one uint32 per element = bf16 hi | bf16 lo<<16
static __device__ uint32_t g_pa[(size_t)NN * DD];    // ping
static __device__ uint32_t g_pb[(size_t)NN * DD];    // pong
static __device__ uint32_t g_pagg[(size_t)NN * DD];  // aggregated
// pre-split W smem image: per layer [2 planes][256 k][136 cols (272B rows)]
static __device__ __align__(16) unsigned short g_WT[(size_t)NL * 69632];
static __device__ float g_invdeg[NN];
static __device__ int   g_cnt[NN];
static __device__ int   g_fill[NN];
static __device__ int   g_rowptr[NN + 1];
static __device__ int   g_csr[NE];
static __device__ int   g_bsums[128];

// ---------------- PTX helpers ----------------------------------------------
__device__ __forceinline__ uint32_t smem_u32(const void* p) {
    uint32_t a;
    asm("{ .reg .u64 t; cvta.to.shared.u64 t, %1; cvt.u32.u64 %0, t; }"
        : "=r"(a) : "l"(p));
    return a;
}
__device__ __forceinline__ void ldsm_x4(uint32_t* r, uint32_t addr) {
    asm volatile("ldmatrix.sync.aligned.m8n8.x4.shared.b16 {%0,%1,%2,%3}, [%4];"
                 : "=r"(r[0]), "=r"(r[1]), "=r"(r[2]), "=r"(r[3]) : "r"(addr));
}
__device__ __forceinline__ void ldsm_x4t(uint32_t* r, uint32_t addr) {
    asm volatile("ldmatrix.sync.aligned.m8n8.x4.trans.shared.b16 {%0,%1,%2,%3}, [%4];"
                 : "=r"(r[0]), "=r"(r[1]), "=r"(r[2]), "=r"(r[3]) : "r"(addr));
}
__device__ __forceinline__ void mma16816(float* d, const uint32_t* a,
                                         uint32_t b0, uint32_t b1) {
    asm volatile(
        "mma.sync.aligned.m16n8k16.row.col.f32.bf16.bf16.f32 "
        "{%0,%1,%2,%3}, {%4,%5,%6,%7}, {%8,%9}, {%0,%1,%2,%3};"
        : "+f"(d[0]), "+f"(d[1]), "+f"(d[2]), "+f"(d[3])
        : "r"(a[0]), "r"(a[1]), "r"(a[2]), "r"(a[3]), "r"(b0), "r"(b1));
}

// ---------------- CSR construction -----------------------------------------
__global__ void k_zero(void) {
    int i = blockIdx.x * blockDim.x + threadIdx.x;
    if (i < NN) { g_cnt[i] = 0; g_fill[i] = 0; }
}
__global__ void k_hist(const int* __restrict__ dst) {
    int e = blockIdx.x * blockDim.x + threadIdx.x;
    if (e < NE) atomicAdd(&g_cnt[dst[e]], 1);
}
#define SCAN_B 1024
__global__ void k_scan1(void) {
    __shared__ int sh[SCAN_B];
    int i = blockIdx.x * SCAN_B + threadIdx.x;
    int v = (i < NN) ? g_cnt[i] : 0;
    sh[threadIdx.x] = v;
    __syncthreads();
    for (int off = 1; off < SCAN_B; off <<= 1) {
        int t = (threadIdx.x >= off) ? sh[threadIdx.x - off] : 0;
        __syncthreads();
        sh[threadIdx.x] += t;
        __syncthreads();
    }
    if (i < NN) g_rowptr[i] = sh[threadIdx.x] - v;
    if (threadIdx.x == SCAN_B - 1) g_bsums[blockIdx.x] = sh[threadIdx.x];
}
__global__ void k_scan2(int nb) {
    if (threadIdx.x == 0 && blockIdx.x == 0) {
        int run = 0;
        for (int i = 0; i < nb; i++) { int v = g_bsums[i]; g_bsums[i] = run; run += v; }
    }
}
__global__ void k_scan3(void) {
    int i = blockIdx.x * blockDim.x + threadIdx.x;
    if (i < NN) {
        g_rowptr[i] += g_bsums[i / SCAN_B];
        int c = g_cnt[i];
        g_invdeg[i] = 1.0f / (float)(c > 0 ? c : 1);
    }
    if (i == 0) g_rowptr[NN] = NE;
}
__global__ void k_scatter(const int* __restrict__ src, const int* __restrict__ dst) {
    int e = blockIdx.x * blockDim.x + threadIdx.x;
    if (e >= NE) return;
    int d = dst[e];
    int pos = atomicAdd(&g_fill[d], 1);
    g_csr[g_rowptr[d] + pos] = src[e];
}

// ---------------- fp32 <-> packed split-bf16 --------------------------------
__device__ __forceinline__ uint32_t packsplit(float v) {
    __nv_bfloat16 hb = __float2bfloat16(v);
    float r = v - __bfloat162float(hb);
    __nv_bfloat16 lb = __float2bfloat16(r);
    return (uint32_t)__bfloat16_as_ushort(hb) |
           ((uint32_t)__bfloat16_as_ushort(lb) << 16);
}
__device__ __forceinline__ float unpacksum(uint32_t p) {
    float2 f = __bfloat1622float2(*(__nv_bfloat162*)&p);
    return f.x + f.y;
}

__global__ void k_split(const float* __restrict__ x, uint32_t* __restrict__ xp) {
    size_t i = ((size_t)blockIdx.x * blockDim.x + threadIdx.x) * 4;
    if (i >= (size_t)NN * DD) return;
    float4 v = *(const float4*)(x + i);
    uint4 o;
    o.x = packsplit(v.x); o.y = packsplit(v.y);
    o.z = packsplit(v.z); o.w = packsplit(v.w);
    *(uint4*)(xp + i) = o;
}

// ---------------- W pre-split into smem image layout ------------------------
__global__ void k_wprep(const float* __restrict__ Wl, const float* __restrict__ Wr) {
    int idx = blockIdx.x * blockDim.x + threadIdx.x;
    if (idx >= NL * 256 * DD) return;
    int l = idx >> 15;
    int rem = idx & 32767;
    int k = rem >> 7;
    int n = rem & 127;
    float w = (k < 128) ? Wl[(size_t)l * 16384 + (size_t)k * 128 + n]
                        : Wr[(size_t)l * 16384 + (size_t)(k - 128) * 128 + n];
    uint32_t p = packsplit(w);
    size_t base = (size_t)l * 69632 + (size_t)k * 136 + n;
    g_WT[base] = (unsigned short)(p & 0xFFFF);
    g_WT[base + 34816] = (unsigned short)(p >> 16);
}

// ---------------- mean aggregation (gather, packed) -------------------------
// one warp per dst node; lane owns 4 packed cols = 1 LDG.128 per edge
__global__ void k_agg(const uint32_t* __restrict__ xp, uint32_t* __restrict__ ap) {
    int node = blockIdx.x * 8 + (threadIdx.x >> 5);
    if (node >= NN) return;
    int lane = threadIdx.x & 31;
    int beg = g_rowptr[node];
    int end = g_rowptr[node + 1];
    float4 acc = make_float4(0.f, 0.f, 0.f, 0.f);
    int t = beg;
    for (; t + 1 < end; t += 2) {
        int s0 = g_csr[t], s1 = g_csr[t + 1];
        uint4 v0 = *(const uint4*)(xp + (size_t)s0 * DD + lane * 4);
        uint4 v1 = *(const uint4*)(xp + (size_t)s1 * DD + lane * 4);
        acc.x += unpacksum(v0.x) + unpacksum(v1.x);
        acc.y += unpacksum(v0.y) + unpacksum(v1.y);
        acc.z += unpacksum(v0.z) + unpacksum(v1.z);
        acc.w += unpacksum(v0.w) + unpacksum(v1.w);
    }
    if (t < end) {
        int s0 = g_csr[t];
        uint4 v0 = *(const uint4*)(xp + (size_t)s0 * DD + lane * 4);
        acc.x += unpacksum(v0.x); acc.y += unpacksum(v0.y);
        acc.z += unpacksum(v0.z); acc.w += unpacksum(v0.w);
    }
    float sc = g_invdeg[node];
    uint4 o;
    o.x = packsplit(acc.x * sc); o.y = packsplit(acc.y * sc);
    o.z = packsplit(acc.z * sc); o.w = packsplit(acc.w * sc);
    *(uint4*)(ap + (size_t)node * DD + lane * 4) = o;
}

// ---------------- persistent mma.sync GEMM ----------------------------------
// Y = [agg|x] @ [Wl;Wr] + b, split-bf16: AhWh + AlWh + AhWl.
// Per tile: 4 packed A chunks (128x64), reg-prefetched, PRMT-split to hi/lo
// smem plane buffers (double buffered); 3 products per chunk vs resident W.
#define SMEM_W    0
#define W_PLANE   69632
#define SMEM_A    139264
#define A_BUF     18432          // one plane buffer: 128 rows * 144B
#define A_PAIR    36864          // hi+lo pair
#define SMEM_BIAS 212992
#define SMEM_TOT  213504

__global__ __launch_bounds__(256, 1)
void k_gemm_tc(const uint32_t* __restrict__ aggp,
               const uint32_t* __restrict__ curp,
               const unsigned short* __restrict__ wt,
               const float* __restrict__ bias,
               uint32_t* __restrict__ outp,
               float* __restrict__ outf, int last) {
    extern __shared__ char smem[];
    const uint32_t sb = smem_u32(smem);
    const int tid = threadIdx.x;
    const int wid = tid >> 5, lane = tid & 31;
    const int warp_m = wid & 3, warp_n = wid >> 2;

    {   // load W smem image (139264 B = 8704 uint4) + bias
        const uint4* s4 = (const uint4*)wt;
        uint4* d4 = (uint4*)(smem + SMEM_W);
        #pragma unroll
        for (int i = 0; i < 34; i++) d4[tid + i * 256] = s4[tid + i * 256];
        if (tid < 128) ((float*)(smem + SMEM_BIAS))[tid] = bias[tid];
    }
    __syncthreads();

    // ldmatrix bases
    const uint32_t aBase = sb + SMEM_A +
        (uint32_t)(warp_m * 32 + (lane & 15)) * 144 + (uint32_t)(lane >> 4) * 16;
    const uint32_t bBase = sb + SMEM_W +
        (uint32_t)(lane & 15) * 272 +
        (uint32_t)(warp_n * 64 + (lane >> 4) * 8) * 2;

    // loader coords: row = tid/2, 32-col half = tid&1
    const int ldRow = tid >> 1;
    const int ldHalf = tid & 1;
    const uint32_t stsH = sb + SMEM_A + (uint32_t)ldRow * 144 + (uint32_t)ldHalf * 64;

    const int nTiles = (NN + 127) / 128;
    uint4 pf[8];

    // prologue prefetch: tile(blockIdx), chunk 0 (agg cols 0..63)
    {
        int row = blockIdx.x * 128 + ldRow;
        if ((int)blockIdx.x < nTiles && row < NN) {
            const uint4* p = (const uint4*)(aggp + (size_t)row * DD + ldHalf * 32);
            #pragma unroll
            for (int i = 0; i < 8; i++) pf[i] = p[i];
        } else {
            #pragma unroll
            for (int i = 0; i < 8; i++) pf[i] = make_uint4(0, 0, 0, 0);
        }
    }

    for (int tile = blockIdx.x; tile < nTiles; tile += (int)gridDim.x) {
        const int rowBase = tile * 128;
        float acc[16][4];
        #pragma unroll
        for (int i = 0; i < 16; i++)
            #pragma unroll
            for (int j = 0; j < 4; j++) acc[i][j] = 0.f;

        #pragma unroll 1
        for (int c = 0; c < 4; c++) {
            const int b = c & 1;
            // split prefetched packed chunk into hi/lo plane buffers
            {
                const uint32_t dH = stsH + (uint32_t)b * A_PAIR;
                const uint32_t dL = dH + A_BUF;
                #pragma unroll
                for (int i = 0; i < 4; i++) {
                    uint4 q0 = pf[2 * i], q1 = pf[2 * i + 1];
                    uint4 hi, lo;
                    hi.x = __byte_perm(q0.x, q0.y, 0x5410);
                    hi.y = __byte_perm(q0.z, q0.w, 0x5410);
                    hi.z = __byte_perm(q1.x, q1.y, 0x5410);
                    hi.w = __byte_perm(q1.z, q1.w, 0x5410);
                    lo.x = __byte_perm(q0.x, q0.y, 0x7632);
                    lo.y = __byte_perm(q0.z, q0.w, 0x7632);
                    lo.z = __byte_perm(q1.x, q1.y, 0x7632);
                    lo.w = __byte_perm(q1.z, q1.w, 0x7632);
                    asm volatile("st.shared.v4.b32 [%0], {%1,%2,%3,%4};"
                                 :: "r"(dH + i * 16), "r"(hi.x), "r"(hi.y), "r"(hi.z), "r"(hi.w) : "memory");
                    asm volatile("st.shared.v4.b32 [%0], {%1,%2,%3,%4};"
                                 :: "r"(dL + i * 16), "r"(lo.x), "r"(lo.y), "r"(lo.z), "r"(lo.w) : "memory");
                }
            }
            // prefetch next chunk (or next tile's chunk 0)
            {
                int nt = tile, nc = c + 1;
                if (nc == 4) { nt = tile + (int)gridDim.x; nc = 0; }
                if (nt < nTiles) {
                    const uint32_t* src = (nc < 2) ? aggp : curp;
                    int row = nt * 128 + ldRow;
                    if (row < NN) {
                        const uint4* p = (const uint4*)(src + (size_t)row * DD +
                                                        (nc & 1) * 64 + ldHalf * 32);
                        #pragma unroll
                        for (int i = 0; i < 8; i++) pf[i] = p[i];
                    } else {
                        #pragma unroll
                        for (int i = 0; i < 8; i++) pf[i] = make_uint4(0, 0, 0, 0);
                    }
                }
            }
            __syncthreads();

            // compute: 3 products for this chunk (K rows c*64..c*64+63)
            const uint32_t aH = aBase + (uint32_t)b * A_PAIR;
            const uint32_t aL = aH + A_BUF;
            const uint32_t wH = bBase + (uint32_t)c * 64 * 272;
            const uint32_t wL = wH + W_PLANE;
            #pragma unroll
            for (int ks = 0; ks < 4; ks++) {
                uint32_t wf[4][4];
                #pragma unroll
                for (int nb = 0; nb < 4; nb++)
                    ldsm_x4t(wf[nb], wH + (uint32_t)ks * 4352 + (uint32_t)nb * 32);
                uint32_t ah[2][4];
                ldsm_x4(ah[0], aH + (uint32_t)ks * 32);
                ldsm_x4(ah[1], aH + (uint32_t)ks * 32 + 16 * 144);
                #pragma unroll
                for (int mi = 0; mi < 2; mi++)
                    #pragma unroll
                    for (int nb = 0; nb < 4; nb++) {
                        mma16816(acc[mi * 8 + nb * 2],     ah[mi], wf[nb][0], wf[nb][1]);
                        mma16816(acc[mi * 8 + nb * 2 + 1], ah[mi], wf[nb][2], wf[nb][3]);
                    }
                uint32_t al[2][4];
                ldsm_x4(al[0], aL + (uint32_t)ks * 32);
                ldsm_x4(al[1], aL + (uint32_t)ks * 32 + 16 * 144);
                #pragma unroll
                for (int mi = 0; mi < 2; mi++)
                    #pragma unroll
                    for (int nb = 0; nb < 4; nb++) {
                        mma16816(acc[mi * 8 + nb * 2],     al[mi], wf[nb][0], wf[nb][1]);
                        mma16816(acc[mi * 8 + nb * 2 + 1], al[mi], wf[nb][2], wf[nb][3]);
                    }
                #pragma unroll
                for (int nb = 0; nb < 4; nb++)
                    ldsm_x4t(wf[nb], wL + (uint32_t)ks * 4352 + (uint32_t)nb * 32);
                #pragma unroll
                for (int mi = 0; mi < 2; mi++)
                    #pragma unroll
                    for (int nb = 0; nb < 4; nb++) {
                        mma16816(acc[mi * 8 + nb * 2],     ah[mi], wf[nb][0], wf[nb][1]);
                        mma16816(acc[mi * 8 + nb * 2 + 1], ah[mi], wf[nb][2], wf[nb][3]);
                    }
            }
        }

        // ---- epilogue: bias (+relu), packed store (or fp32 on last) ----
        const float* bs = (const float*)(smem + SMEM_BIAS);
        const int colBase = warp_n * 64 + (lane & 3) * 2;
        const int rBase = rowBase + warp_m * 32 + (lane >> 2);
        #pragma unroll
        for (int mi = 0; mi < 2; mi++) {
            #pragma unroll
            for (int ni = 0; ni < 8; ni++) {
                const int col = colBase + ni * 8;
                const float b0 = bs[col], b1 = bs[col + 1];
                const float* d = acc[mi * 8 + ni];
                #pragma unroll
                for (int rr = 0; rr < 2; rr++) {
                    const int row = rBase + mi * 16 + rr * 8;
                    if (row < NN) {
                        float v0 = d[rr * 2] + b0;
                        float v1 = d[rr * 2 + 1] + b1;
                        if (last) {
                            *(float2*)(outf + (size_t)row * DD + col) =
                                make_float2(v0, v1);
                        } else {
                            v0 = fmaxf(v0, 0.f); v1 = fmaxf(v1, 0.f);
                            uint2 o;
                            o.x = packsplit(v0);
                            o.y = packsplit(v1);
                            *(uint2*)(outp + (size_t)row * DD + col) = o;
                        }
                    }
                }
            }
        }
    }
}

// ---------------- host driver (graph-capturable) ----------------------------
extern "C" void kernel_launch(void* const* d_in, const int* in_sizes, int n_in,
                              void* d_out, int out_size) {
    const float* x  = (const float*)d_in[0];
    const float* Wl = (const float*)d_in[1];
    const float* Wr = (const float*)d_in[2];
    const float* b  = (const float*)d_in[3];
    const int* ei   = (const int*)d_in[4];
    const int* src  = ei;
    const int* dst  = ei + NE;

    uint32_t *pa, *pb, *pagg;
    unsigned short* wt;
    cudaGetSymbolAddress((void**)&pa, g_pa);
    cudaGetSymbolAddress((void**)&pb, g_pb);
    cudaGetSymbolAddress((void**)&pagg, g_pagg);
    cudaGetSymbolAddress((void**)&wt, g_WT);

    cudaFuncSetAttribute(k_gemm_tc, cudaFuncAttributeMaxDynamicSharedMemorySize, SMEM_TOT);

    const int NB_SCAN = (NN + SCAN_B - 1) / SCAN_B;

    k_zero<<<(NN + 255) / 256, 256>>>();
    k_hist<<<(NE + 255) / 256, 256>>>(dst);
    k_scan1<<<NB_SCAN, SCAN_B>>>();
    k_scan2<<<1, 32>>>(NB_SCAN);
    k_scan3<<<(NN + 255) / 256, 256>>>();
    k_scatter<<<(NE + 255) / 256, 256>>>(src, dst);
    k_split<<<(NN * DD / 4 + 255) / 256, 256>>>(x, pa);
    k_wprep<<<(NL * 256 * DD + 255) / 256, 256>>>(Wl, Wr);

    uint32_t *cur = pa, *nxt = pb;
    for (int i = 0; i < NL; i++) {
        k_agg<<<(NN + 7) / 8, 256>>>(cur, pagg);
        int last = (i == NL - 1) ? 1 : 0;
        k_gemm_tc<<<152, 256, SMEM_TOT>>>(pagg, cur,
                                          wt + (size_t)i * 69632,
                                          b + (size_t)i * DD,
                                          nxt, (float*)d_out, last);
        uint32_t* t = cur; cur = nxt; nxt = t;
    }
}